// round 1
// baseline (speedup 1.0000x reference)
#include <cuda_runtime.h>

#define DMODEL 512
#define NHEAD  8
#define DK     64
#define BATCH  2
#define SEQ    4096
#define MTOT   (BATCH * SEQ)   // 8192

// ---------------- scratch (alloc-free: __device__ globals) ----------------
__device__ float g_q[(size_t)BATCH * NHEAD * SEQ * DK];   // [B,H,T,dk]
__device__ float g_k[(size_t)BATCH * NHEAD * SEQ * DK];
__device__ float g_v[(size_t)BATCH * NHEAD * SEQ * DK];
__device__ float g_att[(size_t)MTOT * DMODEL];            // [B,T,D]

// ---------------------------------------------------------------------------
// NT GEMM: C = A @ W^T.  A[M,K] row-major, W[N,K] row-major, K = DMODEL = 512.
// Tile 64x64, BK=16, 256 threads, 4x4 microtile per thread.
// MODE 0: scatter output into per-head layout [B,H,T,dk]  (for Q/K/V proj)
// MODE 1: plain row-major C[M,N]                          (for O proj)
// ---------------------------------------------------------------------------
template <int MODE>
__launch_bounds__(256)
__global__ void gemm_nt(const float* __restrict__ A,
                        const float* __restrict__ W,
                        float* __restrict__ C)
{
    const int K = DMODEL;
    __shared__ float As[16][68];   // [k][m], pad 4 keeps float4 alignment
    __shared__ float Ws[16][68];   // [k][n]

    const int tid = threadIdx.x;
    const int tx = tid & 15;       // n direction
    const int ty = tid >> 4;       // m direction
    const int m0 = blockIdx.y * 64;
    const int n0 = blockIdx.x * 64;

    const int lr = tid >> 2;            // 0..63 row within tile
    const int lk = (tid & 3) << 2;      // 0,4,8,12

    float acc[4][4] = {};

    for (int k0 = 0; k0 < K; k0 += 16) {
        float4 a = *(const float4*)(A + (size_t)(m0 + lr) * K + k0 + lk);
        float4 w = *(const float4*)(W + (size_t)(n0 + lr) * K + k0 + lk);
        As[lk + 0][lr] = a.x; As[lk + 1][lr] = a.y;
        As[lk + 2][lr] = a.z; As[lk + 3][lr] = a.w;
        Ws[lk + 0][lr] = w.x; Ws[lk + 1][lr] = w.y;
        Ws[lk + 2][lr] = w.z; Ws[lk + 3][lr] = w.w;
        __syncthreads();

        #pragma unroll
        for (int kk = 0; kk < 16; ++kk) {
            float4 av = *(const float4*)&As[kk][ty << 2];
            float4 wv = *(const float4*)&Ws[kk][tx << 2];
            float am[4] = {av.x, av.y, av.z, av.w};
            float wn[4] = {wv.x, wv.y, wv.z, wv.w};
            #pragma unroll
            for (int i = 0; i < 4; ++i)
                #pragma unroll
                for (int j = 0; j < 4; ++j)
                    acc[i][j] += am[i] * wn[j];
        }
        __syncthreads();
    }

    #pragma unroll
    for (int i = 0; i < 4; ++i) {
        const int m = m0 + (ty << 2) + i;
        float4 r = make_float4(acc[i][0], acc[i][1], acc[i][2], acc[i][3]);
        if (MODE == 0) {
            // n = n0 + 4*tx + j ; head = n0/64 (n0 multiple of 64, DK=64)
            const int h = n0 >> 6;
            const int b = m / SEQ;
            const int t = m - b * SEQ;
            *(float4*)(C + (((size_t)(b * NHEAD + h) * SEQ + t) * DK) + (tx << 2)) = r;
        } else {
            *(float4*)(C + (size_t)m * DMODEL + n0 + (tx << 2)) = r;
        }
    }
}

// ---------------------------------------------------------------------------
// Flash attention, fp32. One block = one (b,h) x 64-row query tile.
// 256 threads (16x16), 4x4 microtiles for both S=QK^T and O+=PV.
// Online softmax in exp2 domain (scale folded into log2(e)/sqrt(dk)).
// ---------------------------------------------------------------------------
__launch_bounds__(256)
__global__ void flash_attn(const float* __restrict__ Q,
                           const float* __restrict__ Kg,
                           const float* __restrict__ Vg,
                           float* __restrict__ O)
{
    extern __shared__ float sm[];
    float (*qs)[68] = (float(*)[68])(sm);              // [d][q]  64x68
    float (*ks)[68] = (float(*)[68])(sm + 64 * 68);    // [d][k]
    float (*vs)[68] = (float(*)[68])(sm + 2 * 64 * 68);// [k][d]
    float (*ps)[68] = (float(*)[68])(sm + 3 * 64 * 68);// [q][k]

    const int tid = threadIdx.x;
    const int tx = tid & 15;   // k-col group for S, d-col group for PV
    const int ty = tid >> 4;   // q-row group

    const int qt = blockIdx.x;
    const int bh = blockIdx.y;

    const float* qb = Q  + ((size_t)bh * SEQ + qt * 64) * DK;
    const float* kb = Kg + (size_t)bh * SEQ * DK;
    const float* vb = Vg + (size_t)bh * SEQ * DK;

    // load Q tile transposed: qs[d][t]
    #pragma unroll
    for (int it = 0; it < 4; ++it) {
        int idx = tid + it * 256;          // 0..1023
        int r = idx >> 4;                  // t row 0..63
        int c = (idx & 15) << 2;           // d col
        float4 a = *(const float4*)(qb + r * DK + c);
        qs[c + 0][r] = a.x; qs[c + 1][r] = a.y;
        qs[c + 2][r] = a.z; qs[c + 3][r] = a.w;
    }

    float mrow[4], lrow[4], acc[4][4] = {};
    #pragma unroll
    for (int i = 0; i < 4; ++i) { mrow[i] = -1e30f; lrow[i] = 0.f; }

    const float sc = 1.4426950408889634f * 0.125f;   // log2(e)/sqrt(64)

    for (int kt = 0; kt < SEQ / 64; ++kt) {
        __syncthreads();   // prior PV done before overwriting ks/vs
        const float* kp = kb + (size_t)kt * 64 * DK;
        const float* vp = vb + (size_t)kt * 64 * DK;
        #pragma unroll
        for (int it = 0; it < 4; ++it) {
            int idx = tid + it * 256;
            int r = idx >> 4;
            int c = (idx & 15) << 2;
            float4 kv4 = *(const float4*)(kp + r * DK + c);
            ks[c + 0][r] = kv4.x; ks[c + 1][r] = kv4.y;
            ks[c + 2][r] = kv4.z; ks[c + 3][r] = kv4.w;
            float4 vv4 = *(const float4*)(vp + r * DK + c);
            *(float4*)&vs[r][c] = vv4;
        }
        __syncthreads();

        // S = Q K^T  (64x64, reduce over d)
        float s[4][4] = {};
        #pragma unroll
        for (int d = 0; d < DK; ++d) {
            float4 av = *(const float4*)&qs[d][ty << 2];
            float4 bv = *(const float4*)&ks[d][tx << 2];
            float am[4] = {av.x, av.y, av.z, av.w};
            float bn[4] = {bv.x, bv.y, bv.z, bv.w};
            #pragma unroll
            for (int i = 0; i < 4; ++i)
                #pragma unroll
                for (int j = 0; j < 4; ++j)
                    s[i][j] += am[i] * bn[j];
        }

        // online softmax (exp2 domain), row groups are 16 contiguous lanes
        #pragma unroll
        for (int i = 0; i < 4; ++i) {
            #pragma unroll
            for (int j = 0; j < 4; ++j) s[i][j] *= sc;
            float mx = fmaxf(fmaxf(s[i][0], s[i][1]), fmaxf(s[i][2], s[i][3]));
            #pragma unroll
            for (int off = 8; off > 0; off >>= 1)
                mx = fmaxf(mx, __shfl_xor_sync(0xffffffffu, mx, off));
            float mnew = fmaxf(mrow[i], mx);
            float corr = exp2f(mrow[i] - mnew);
            mrow[i] = mnew;
            float rs = 0.f;
            #pragma unroll
            for (int j = 0; j < 4; ++j) {
                float p = exp2f(s[i][j] - mnew);
                s[i][j] = p;
                rs += p;
            }
            #pragma unroll
            for (int off = 8; off > 0; off >>= 1)
                rs += __shfl_xor_sync(0xffffffffu, rs, off);
            lrow[i] = lrow[i] * corr + rs;
            #pragma unroll
            for (int j = 0; j < 4; ++j) acc[i][j] *= corr;
            *(float4*)&ps[(ty << 2) + i][tx << 2] =
                make_float4(s[i][0], s[i][1], s[i][2], s[i][3]);
        }
        __syncthreads();

        // O += P V  (reduce over k; P row reads broadcast across tx)
        #pragma unroll
        for (int kk = 0; kk < 64; ++kk) {
            float4 bv = *(const float4*)&vs[kk][tx << 2];
            #pragma unroll
            for (int i = 0; i < 4; ++i) {
                float a = ps[(ty << 2) + i][kk];
                acc[i][0] += a * bv.x;
                acc[i][1] += a * bv.y;
                acc[i][2] += a * bv.z;
                acc[i][3] += a * bv.w;
            }
        }
    }

    // epilogue: normalize and write [B,T,D] with heads re-interleaved
    const int b = bh / NHEAD;
    const int h = bh - b * NHEAD;
    #pragma unroll
    for (int i = 0; i < 4; ++i) {
        float inv = 1.f / lrow[i];
        int t = qt * 64 + (ty << 2) + i;
        float4 r = make_float4(acc[i][0] * inv, acc[i][1] * inv,
                               acc[i][2] * inv, acc[i][3] * inv);
        *(float4*)(O + ((size_t)(b * SEQ + t)) * DMODEL + h * DK + (tx << 2)) = r;
    }
}

// ---------------------------------------------------------------------------
extern "C" void kernel_launch(void* const* d_in, const int* in_sizes, int n_in,
                              void* d_out, int out_size)
{
    const float* x  = (const float*)d_in[0];
    const float* Wq = (const float*)d_in[1];
    const float* Wk = (const float*)d_in[2];
    const float* Wv = (const float*)d_in[3];
    const float* Wo = (const float*)d_in[4];
    float* out = (float*)d_out;

    float *q, *k, *v, *att;
    cudaGetSymbolAddress((void**)&q,   g_q);
    cudaGetSymbolAddress((void**)&k,   g_k);
    cudaGetSymbolAddress((void**)&v,   g_v);
    cudaGetSymbolAddress((void**)&att, g_att);

    dim3 gg(DMODEL / 64, MTOT / 64);   // (8, 128)
    gemm_nt<0><<<gg, 256>>>(x, Wq, q);
    gemm_nt<0><<<gg, 256>>>(x, Wk, k);
    gemm_nt<0><<<gg, 256>>>(x, Wv, v);

    const int smem = 4 * 64 * 68 * (int)sizeof(float);  // 69632 B
    cudaFuncSetAttribute(flash_attn,
                         cudaFuncAttributeMaxDynamicSharedMemorySize, smem);
    flash_attn<<<dim3(SEQ / 64, BATCH * NHEAD), 256, smem>>>(q, k, v, att);

    gemm_nt<1><<<gg, 256>>>(att, Wo, out);
}

// round 17
// speedup vs baseline: 1.0043x; 1.0043x over previous
#include <cuda_runtime.h>
#include <cstdint>

#define DMODEL 512
#define NHEAD  8
#define DK     64
#define BATCH  2
#define SEQ    4096
#define MTOT   (BATCH * SEQ)   // 8192

// ---------------- scratch (alloc-free: __device__ globals) ----------------
__device__ float g_q[(size_t)BATCH * NHEAD * SEQ * DK];   // [B,H,T,dk]
__device__ float g_k[(size_t)BATCH * NHEAD * SEQ * DK];
__device__ float g_v[(size_t)BATCH * NHEAD * SEQ * DK];
__device__ float g_att[(size_t)MTOT * DMODEL];            // [B,T,D]

// ---------------- f32x2 packed helpers (legal on this target) --------------
typedef unsigned long long ull;
__device__ __forceinline__ ull pk2(float x) {
    ull r; uint32_t u = __float_as_uint(x);
    asm("mov.b64 %0, {%1, %1};" : "=l"(r) : "r"(u));
    return r;
}
__device__ __forceinline__ float2 up2(ull v) {
    float2 r;
    asm("mov.b64 {%0, %1}, %2;" : "=f"(r.x), "=f"(r.y) : "l"(v));
    return r;
}
__device__ __forceinline__ void ffma2(ull& d, ull a, ull b) {
    asm("fma.rn.f32x2 %0, %1, %2, %0;" : "+l"(d) : "l"(a), "l"(b));
}
__device__ __forceinline__ void fmul2(ull& d, ull a) {
    asm("mul.rn.f32x2 %0, %0, %1;" : "+l"(d) : "l"(a));
}
__device__ __forceinline__ float ex2(float x) {
    float y; asm("ex2.approx.ftz.f32 %0, %1;" : "=f"(y) : "f"(x));
    return y;
}

// ---------------------------------------------------------------------------
// NT GEMM: C = A @ W^T.  A[M,K] row-major, W[N,K] row-major, K = DMODEL = 512.
// Tile 64x64, BK=16, 256 threads, 4x4 microtile via packed fma.rn.f32x2.
// MODE 0: scatter output into per-head layout [B,H,T,dk]  (for Q/K/V proj)
// MODE 1: plain row-major C[M,N]                          (for O proj)
// Ws rows are 68 floats = 272 B = 17*16 B, so 16 B-aligned ulonglong2 reads.
// ---------------------------------------------------------------------------
template <int MODE>
__launch_bounds__(256)
__global__ void gemm_nt(const float* __restrict__ A,
                        const float* __restrict__ W,
                        float* __restrict__ C)
{
    const int K = DMODEL;
    __shared__ float As[16][68];   // [k][m]
    __shared__ float Ws[16][68];   // [k][n]

    const int tid = threadIdx.x;
    const int tx = tid & 15;       // n direction
    const int ty = tid >> 4;       // m direction
    const int m0 = blockIdx.y * 64;
    const int n0 = blockIdx.x * 64;

    const int lr = tid >> 2;            // 0..63 row within tile
    const int lk = (tid & 3) << 2;      // 0,4,8,12

    ull accp[4][2] = {};                // [i][j-pair] packed accumulators

    for (int k0 = 0; k0 < K; k0 += 16) {
        float4 a = *(const float4*)(A + (size_t)(m0 + lr) * K + k0 + lk);
        float4 w = *(const float4*)(W + (size_t)(n0 + lr) * K + k0 + lk);
        As[lk + 0][lr] = a.x; As[lk + 1][lr] = a.y;
        As[lk + 2][lr] = a.z; As[lk + 3][lr] = a.w;
        Ws[lk + 0][lr] = w.x; Ws[lk + 1][lr] = w.y;
        Ws[lk + 2][lr] = w.z; Ws[lk + 3][lr] = w.w;
        __syncthreads();

        #pragma unroll
        for (int kk = 0; kk < 16; ++kk) {
            ulonglong2 wv = *(const ulonglong2*)&Ws[kk][tx << 2];
            float4 av = *(const float4*)&As[kk][ty << 2];
            ull a0 = pk2(av.x), a1 = pk2(av.y), a2 = pk2(av.z), a3 = pk2(av.w);
            ffma2(accp[0][0], a0, wv.x); ffma2(accp[0][1], a0, wv.y);
            ffma2(accp[1][0], a1, wv.x); ffma2(accp[1][1], a1, wv.y);
            ffma2(accp[2][0], a2, wv.x); ffma2(accp[2][1], a2, wv.y);
            ffma2(accp[3][0], a3, wv.x); ffma2(accp[3][1], a3, wv.y);
        }
        __syncthreads();
    }

    #pragma unroll
    for (int i = 0; i < 4; ++i) {
        const int m = m0 + (ty << 2) + i;
        float2 c01 = up2(accp[i][0]);
        float2 c23 = up2(accp[i][1]);
        float4 r = make_float4(c01.x, c01.y, c23.x, c23.y);
        if (MODE == 0) {
            const int h = n0 >> 6;
            const int b = m >> 12;
            const int t = m & 4095;
            *(float4*)(C + (((size_t)(b * NHEAD + h) * SEQ + t) * DK) + (tx << 2)) = r;
        } else {
            *(float4*)(C + (size_t)m * DMODEL + n0 + (tx << 2)) = r;
        }
    }
}

// ===========================================================================
// Flash attention fp32, inner loops on packed fma.rn.f32x2.
// One block = one (b,h) x 64-row q-tile. 256 threads (16x16), 4x4 microtile.
// ===========================================================================
__launch_bounds__(256)
__global__ void flash_attn(const float* __restrict__ Q,
                           const float* __restrict__ Kg,
                           const float* __restrict__ Vg,
                           float* __restrict__ O)
{
    extern __shared__ float sm[];
    float (*qs)[68] = (float(*)[68])(sm);               // [d][q]
    float (*ks)[68] = (float(*)[68])(sm + 64 * 68);     // [d][k]
    float (*vs)[68] = (float(*)[68])(sm + 2 * 64 * 68); // [k][d]
    float (*ps)[68] = (float(*)[68])(sm + 3 * 64 * 68); // [q][k]

    const int tid = threadIdx.x;
    const int tx = tid & 15;
    const int ty = tid >> 4;

    const int qt = blockIdx.x;
    const int bh = blockIdx.y;

    const float* qb = Q  + ((size_t)bh * SEQ + qt * 64) * DK;
    const float* kb = Kg + (size_t)bh * SEQ * DK;
    const float* vb = Vg + (size_t)bh * SEQ * DK;

    const float sc = 1.4426950408889634f * 0.125f;   // log2(e)/sqrt(64)

    // load Q tile transposed and pre-scaled: qs[d][t] = sc * q
    #pragma unroll
    for (int it = 0; it < 4; ++it) {
        int idx = tid + it * 256;
        int r = idx >> 4;
        int c = (idx & 15) << 2;
        float4 a = *(const float4*)(qb + r * DK + c);
        qs[c + 0][r] = a.x * sc; qs[c + 1][r] = a.y * sc;
        qs[c + 2][r] = a.z * sc; qs[c + 3][r] = a.w * sc;
    }

    float mrow[4], lrow[4];
    ull accp[4][2] = {};
    #pragma unroll
    for (int i = 0; i < 4; ++i) { mrow[i] = -1e30f; lrow[i] = 0.f; }

    for (int kt = 0; kt < SEQ / 64; ++kt) {
        __syncthreads();
        const float* kp = kb + (size_t)kt * 64 * DK;
        const float* vp = vb + (size_t)kt * 64 * DK;
        #pragma unroll
        for (int it = 0; it < 4; ++it) {
            int idx = tid + it * 256;
            int r = idx >> 4;
            int c = (idx & 15) << 2;
            float4 kv4 = *(const float4*)(kp + r * DK + c);
            ks[c + 0][r] = kv4.x; ks[c + 1][r] = kv4.y;
            ks[c + 2][r] = kv4.z; ks[c + 3][r] = kv4.w;
            float4 vv4 = *(const float4*)(vp + r * DK + c);
            *(float4*)&vs[r][c] = vv4;
        }
        __syncthreads();

        // S = (sc*Q) K^T via FFMA2
        ull sp[4][2] = {};
        #pragma unroll
        for (int d = 0; d < DK; ++d) {
            ulonglong2 bv = *(const ulonglong2*)&ks[d][tx << 2];
            float4 av = *(const float4*)&qs[d][ty << 2];
            ull a0 = pk2(av.x), a1 = pk2(av.y), a2 = pk2(av.z), a3 = pk2(av.w);
            ffma2(sp[0][0], a0, bv.x); ffma2(sp[0][1], a0, bv.y);
            ffma2(sp[1][0], a1, bv.x); ffma2(sp[1][1], a1, bv.y);
            ffma2(sp[2][0], a2, bv.x); ffma2(sp[2][1], a2, bv.y);
            ffma2(sp[3][0], a3, bv.x); ffma2(sp[3][1], a3, bv.y);
        }

        // online softmax (exp2 domain)
        #pragma unroll
        for (int i = 0; i < 4; ++i) {
            float2 s01 = up2(sp[i][0]);
            float2 s23 = up2(sp[i][1]);
            float s0 = s01.x, s1 = s01.y, s2 = s23.x, s3 = s23.y;
            float mx = fmaxf(fmaxf(s0, s1), fmaxf(s2, s3));
            #pragma unroll
            for (int off = 8; off > 0; off >>= 1)
                mx = fmaxf(mx, __shfl_xor_sync(0xffffffffu, mx, off));
            float mnew = fmaxf(mrow[i], mx);
            float corr = ex2(mrow[i] - mnew);
            mrow[i] = mnew;
            float p0 = ex2(s0 - mnew), p1 = ex2(s1 - mnew);
            float p2 = ex2(s2 - mnew), p3 = ex2(s3 - mnew);
            float rs = (p0 + p1) + (p2 + p3);
            #pragma unroll
            for (int off = 8; off > 0; off >>= 1)
                rs += __shfl_xor_sync(0xffffffffu, rs, off);
            lrow[i] = lrow[i] * corr + rs;
            ull cp = pk2(corr);
            fmul2(accp[i][0], cp);
            fmul2(accp[i][1], cp);
            *(float4*)&ps[(ty << 2) + i][tx << 2] = make_float4(p0, p1, p2, p3);
        }
        __syncthreads();

        // O += P V via FFMA2, kk unrolled by 4 so ps reads are LDS.128
        #pragma unroll
        for (int kk = 0; kk < 64; kk += 4) {
            float pr[4][4];
            #pragma unroll
            for (int i = 0; i < 4; ++i) {
                float4 t = *(const float4*)&ps[(ty << 2) + i][kk];
                pr[i][0] = t.x; pr[i][1] = t.y; pr[i][2] = t.z; pr[i][3] = t.w;
            }
            #pragma unroll
            for (int u = 0; u < 4; ++u) {
                ulonglong2 bv = *(const ulonglong2*)&vs[kk + u][tx << 2];
                #pragma unroll
                for (int i = 0; i < 4; ++i) {
                    ull a = pk2(pr[i][u]);
                    ffma2(accp[i][0], a, bv.x);
                    ffma2(accp[i][1], a, bv.y);
                }
            }
        }
    }

    // epilogue
    const int b = bh / NHEAD;
    const int h = bh - b * NHEAD;
    #pragma unroll
    for (int i = 0; i < 4; ++i) {
        float inv = 1.f / lrow[i];
        int t = qt * 64 + (ty << 2) + i;
        float2 a01 = up2(accp[i][0]);
        float2 a23 = up2(accp[i][1]);
        float4 r = make_float4(a01.x * inv, a01.y * inv, a23.x * inv, a23.y * inv);
        *(float4*)(O + ((size_t)(b * SEQ + t)) * DMODEL + h * DK + (tx << 2)) = r;
    }
}

// ---------------------------------------------------------------------------
extern "C" void kernel_launch(void* const* d_in, const int* in_sizes, int n_in,
                              void* d_out, int out_size)
{
    const float* x  = (const float*)d_in[0];
    const float* Wq = (const float*)d_in[1];
    const float* Wk = (const float*)d_in[2];
    const float* Wv = (const float*)d_in[3];
    const float* Wo = (const float*)d_in[4];
    float* out = (float*)d_out;

    float *q, *k, *v, *att;
    cudaGetSymbolAddress((void**)&q,   g_q);
    cudaGetSymbolAddress((void**)&k,   g_k);
    cudaGetSymbolAddress((void**)&v,   g_v);
    cudaGetSymbolAddress((void**)&att, g_att);

    dim3 gg(DMODEL / 64, MTOT / 64);   // (8, 128)
    gemm_nt<0><<<gg, 256>>>(x, Wq, q);
    gemm_nt<0><<<gg, 256>>>(x, Wk, k);
    gemm_nt<0><<<gg, 256>>>(x, Wv, v);

    const int fsm = 4 * 64 * 68 * (int)sizeof(float);  // 69632 B
    cudaFuncSetAttribute(flash_attn,
                         cudaFuncAttributeMaxDynamicSharedMemorySize, fsm);
    flash_attn<<<dim3(SEQ / 64, BATCH * NHEAD), 256, fsm>>>(q, k, v, att);

    gemm_nt<1><<<gg, 256>>>(att, Wo, out);
}